// round 6
// baseline (speedup 1.0000x reference)
#include <cuda_runtime.h>
#include <cuda_bf16.h>
#include <cstdint>
#include <float.h>

#define CDIM 256
#define HW   4096
#define NVEC 65536
#define NE   1024
#define LOSS_OFF 16777216
#define IDX_OFF  16777217

// ---------------- scratch ----------------
__device__ __nv_bfloat16 d_zhi[(size_t)NVEC * CDIM];
__device__ __nv_bfloat16 d_zlo[(size_t)NVEC * CDIM];
__device__ __nv_bfloat16 d_chi[NE * CDIM];
__device__ __nv_bfloat16 d_clo[NE * CDIM];
__device__ float d_cnorm[NE];
__device__ float d_zn[NVEC];
__device__ float d_smin[NVEC];
__device__ int   d_sidx[NVEC];
__device__ int   d_cand[(size_t)NVEC * 24];
__device__ int   d_amb[NVEC];
__device__ int   d_count;

// ---------------- PTX helpers ----------------
__device__ __forceinline__ unsigned smem_u32(const void* p) {
    return (unsigned)__cvta_generic_to_shared(p);
}
__device__ __forceinline__ void cp_async16(unsigned s, const void* g) {
    asm volatile("cp.async.cg.shared.global [%0], [%1], 16;\n" :: "r"(s), "l"(g));
}
__device__ __forceinline__ void cp_commit() {
    asm volatile("cp.async.commit_group;\n" ::: "memory");
}
__device__ __forceinline__ void cp_wait0() {
    asm volatile("cp.async.wait_group 0;\n" ::: "memory");
}
__device__ __forceinline__ void ldsm4(unsigned* r, unsigned addr) {
    asm volatile("ldmatrix.sync.aligned.m8n8.x4.shared.b16 {%0,%1,%2,%3}, [%4];"
                 : "=r"(r[0]), "=r"(r[1]), "=r"(r[2]), "=r"(r[3]) : "r"(addr));
}
__device__ __forceinline__ void mma16816(float* d, const unsigned* a,
                                         unsigned b0, unsigned b1) {
    asm volatile(
        "mma.sync.aligned.m16n8k16.row.col.f32.bf16.bf16.f32 "
        "{%0,%1,%2,%3}, {%4,%5,%6,%7}, {%8,%9}, {%0,%1,%2,%3};"
        : "+f"(d[0]), "+f"(d[1]), "+f"(d[2]), "+f"(d[3])
        : "r"(a[0]), "r"(a[1]), "r"(a[2]), "r"(a[3]), "r"(b0), "r"(b1));
}

__device__ __forceinline__ void ins3(float s, int j, float& v0, int& i0,
                                     float& v1, int& i1, float& v2, int& i2) {
    if (s < v0 || (s == v0 && j < i0)) {
        v2 = v1; i2 = i1; v1 = v0; i1 = i0; v0 = s; i0 = j;
    } else if (s < v1 || (s == v1 && j < i1)) {
        v2 = v1; i2 = i1; v1 = s; i1 = j;
    } else if (s < v2 || (s == v2 && j < i2)) {
        v2 = s; i2 = j;
    }
}
__device__ __forceinline__ void ins2(float s, int j, float& v0, int& i0,
                                     float& v1, int& i1) {
    if (s < v0 || (s == v0 && j < i0)) { v1 = v0; i1 = i0; v0 = s; i0 = j; }
    else if (s < v1 || (s == v1 && j < i1)) { v1 = s; i1 = j; }
}

// ---------------- kernel 1a: exact codebook norms + counter reset ----------
__global__ void k_cnorm(const float* __restrict__ cb) {
    int j = blockIdx.x * blockDim.x + threadIdx.x;
    if (j == 0) d_count = 0;
    if (j >= NE) return;
    const float* row = cb + (size_t)j * CDIM;
    float s = 0.f;
    for (int k = 0; k < CDIM; ++k) {
        float v = row[k];
        s = __fadd_rn(s, __fmul_rn(v, v));
    }
    d_cnorm[j] = s;
}

// ---------------- kernel 1b: codebook -> bf16 hi/lo ----------------
__global__ void k_cbconv(const float* __restrict__ cb) {
    int j = blockIdx.x, k = threadIdx.x;
    float v = cb[j * CDIM + k];
    __nv_bfloat16 hi = __float2bfloat16(v);
    float r = v - __bfloat162float(hi);
    d_chi[j * CDIM + k] = hi;
    d_clo[j * CDIM + k] = __float2bfloat16(r);
}

// ---------------- kernel 1c: z transpose -> bf16 hi/lo [i][k] --------------
__global__ void k_convert(const float* __restrict__ z) {
    __shared__ float t[32][33];
    int k0 = blockIdx.x * 32, p0 = blockIdx.y * 32, b = blockIdx.z;
    int x = threadIdx.x, y = threadIdx.y;
#pragma unroll
    for (int yy = y; yy < 32; yy += 8)
        t[yy][x] = z[((size_t)b << 20) + ((size_t)(k0 + yy) << 12) + p0 + x];
    __syncthreads();
#pragma unroll
    for (int yy = y; yy < 32; yy += 8) {
        float v = t[x][yy];
        __nv_bfloat16 hi = __float2bfloat16(v);
        float r = v - __bfloat162float(hi);
        size_t i = ((size_t)b << 12) + p0 + yy;
        d_zhi[i * CDIM + k0 + x] = hi;
        d_zlo[i * CDIM + k0 + x] = __float2bfloat16(r);
    }
}

// ---------------- kernel 1d: z row norms (loss only) ----------------
__global__ void k_znorm(const float* __restrict__ z) {
    int i = blockIdx.x * blockDim.x + threadIdx.x;
    int b = i >> 12, p = i & 4095;
    const float* base = z + ((size_t)b << 20) + p;
    float s = 0.f;
#pragma unroll 8
    for (int k = 0; k < CDIM; ++k) {
        float v = base[(size_t)k << 12];
        s += v * v;
    }
    d_zn[i] = s;
}

// ---------------- kernel 2: HMMA 3-pass bf16-split GEMM + top-3/tile -------
// CTA: 128 rows x 8 N-tiles of 128; 8 warps, warp w = rows w*16..w*16+15.
// K chunks of 64 via cp.async, single-buffered; XOR-16B smem swizzle.
#define SM_AHI 0u
#define SM_ALO 16384u
#define SM_BHI 32768u
#define SM_BLO 49152u
#define SM_CN  65536u
#define SM_TOTAL 66048

__global__ __launch_bounds__(256, 2) void k_main_mma() {
    extern __shared__ __align__(128) char smem[];
    const unsigned sb = smem_u32(smem);
    float* cn_sm = (float*)(smem + SM_CN);
    const int tid = threadIdx.x, wid = tid >> 5, lane = tid & 31;
    const int m0 = blockIdx.x * 128;

    // global top-2 for this thread's two rows (rA = m0+wid*16+(lane>>2), rB = rA+8)
    float gva0 = FLT_MAX, gva1 = FLT_MAX, gvb0 = FLT_MAX, gvb1 = FLT_MAX;
    int   gia0 = 0x7fffffff, gia1 = 0x7fffffff, gib0 = 0x7fffffff, gib1 = 0x7fffffff;

    for (int nt = 0; nt < 8; ++nt) {
        const int j0 = nt * 128;
        __syncthreads();                      // prior epilogue done (cn_sm, tiles)
        if (tid < 128) cn_sm[tid] = d_cnorm[j0 + tid];

        float acc[16][4];
#pragma unroll
        for (int a = 0; a < 16; ++a)
#pragma unroll
            for (int q = 0; q < 4; ++q) acc[a][q] = 0.f;

        for (int kc = 0; kc < 4; ++kc) {
            if (kc > 0) __syncthreads();      // prev chunk compute done
            // stage A (z rows) and B (codebook rows), hi+lo, swizzled
#pragma unroll
            for (int q = 0; q < 4; ++q) {
                int u = q * 256 + tid;        // 0..1023
                int row = u >> 3, w8 = u & 7;
                unsigned dst = (unsigned)(row * 128 + ((w8 * 16) ^ ((row & 7) << 4)));
                size_t goff = (size_t)(m0 + row) * CDIM + kc * 64 + w8 * 8;
                cp_async16(sb + SM_AHI + dst, d_zhi + goff);
                cp_async16(sb + SM_ALO + dst, d_zlo + goff);
                size_t boff = (size_t)(j0 + row) * CDIM + kc * 64 + w8 * 8;
                cp_async16(sb + SM_BHI + dst, d_chi + boff);
                cp_async16(sb + SM_BLO + dst, d_clo + boff);
            }
            cp_commit();
            cp_wait0();
            __syncthreads();

#pragma unroll
            for (int ks = 0; ks < 4; ++ks) {
                unsigned ahi[4], alo[4];
                {
                    int arow = wid * 16 + (lane & 15);
                    unsigned kb = (unsigned)(ks * 32 + ((lane >> 4) << 4));
                    unsigned off = (unsigned)(arow * 128 + (kb ^ ((arow & 7) << 4)));
                    ldsm4(ahi, sb + SM_AHI + off);
                    ldsm4(alo, sb + SM_ALO + off);
                }
#pragma unroll
                for (int p = 0; p < 8; ++p) {
                    int brow = p * 16 + (lane & 7) + ((lane >> 4) << 3);
                    unsigned kb = (unsigned)(ks * 32 + (((lane >> 3) & 1) << 4));
                    unsigned off = (unsigned)(brow * 128 + (kb ^ ((brow & 7) << 4)));
                    unsigned bh[4], bl[4];
                    ldsm4(bh, sb + SM_BHI + off);
                    ldsm4(bl, sb + SM_BLO + off);
                    mma16816(acc[2 * p],     ahi, bh[0], bh[1]);
                    mma16816(acc[2 * p + 1], ahi, bh[2], bh[3]);
                    mma16816(acc[2 * p],     ahi, bl[0], bl[1]);
                    mma16816(acc[2 * p + 1], ahi, bl[2], bl[3]);
                    mma16816(acc[2 * p],     alo, bh[0], bh[1]);
                    mma16816(acc[2 * p + 1], alo, bh[2], bh[3]);
                }
            }
        }

        // ---- epilogue: per-row top-3 over this 128-wide tile ----
        float a0 = FLT_MAX, a1 = FLT_MAX, a2 = FLT_MAX;
        float b0 = FLT_MAX, b1 = FLT_MAX, b2 = FLT_MAX;
        int ai0 = 0x7fffffff, ai1 = 0x7fffffff, ai2 = 0x7fffffff;
        int bi0 = 0x7fffffff, bi1 = 0x7fffffff, bi2 = 0x7fffffff;
#pragma unroll
        for (int at = 0; at < 16; ++at) {
            int cc = at * 8 + (lane & 3) * 2;
            float cn0 = cn_sm[cc], cn1 = cn_sm[cc + 1];
            int j = j0 + cc;
            ins3(cn0 - 2.f * acc[at][0], j,     a0, ai0, a1, ai1, a2, ai2);
            ins3(cn1 - 2.f * acc[at][1], j + 1, a0, ai0, a1, ai1, a2, ai2);
            ins3(cn0 - 2.f * acc[at][2], j,     b0, bi0, b1, bi1, b2, bi2);
            ins3(cn1 - 2.f * acc[at][3], j + 1, b0, bi0, b1, bi1, b2, bi2);
        }
#pragma unroll
        for (int o = 1; o <= 2; o <<= 1) {
            float w0 = __shfl_xor_sync(0xffffffffu, a0, o);
            int   wi0 = __shfl_xor_sync(0xffffffffu, ai0, o);
            float w1 = __shfl_xor_sync(0xffffffffu, a1, o);
            int   wi1 = __shfl_xor_sync(0xffffffffu, ai1, o);
            float w2 = __shfl_xor_sync(0xffffffffu, a2, o);
            int   wi2 = __shfl_xor_sync(0xffffffffu, ai2, o);
            ins3(w0, wi0, a0, ai0, a1, ai1, a2, ai2);
            ins3(w1, wi1, a0, ai0, a1, ai1, a2, ai2);
            ins3(w2, wi2, a0, ai0, a1, ai1, a2, ai2);
            w0 = __shfl_xor_sync(0xffffffffu, b0, o);
            wi0 = __shfl_xor_sync(0xffffffffu, bi0, o);
            w1 = __shfl_xor_sync(0xffffffffu, b1, o);
            wi1 = __shfl_xor_sync(0xffffffffu, bi1, o);
            w2 = __shfl_xor_sync(0xffffffffu, b2, o);
            wi2 = __shfl_xor_sync(0xffffffffu, bi2, o);
            ins3(w0, wi0, b0, bi0, b1, bi1, b2, bi2);
            ins3(w1, wi1, b0, bi0, b1, bi1, b2, bi2);
            ins3(w2, wi2, b0, bi0, b1, bi1, b2, bi2);
        }
        if ((lane & 3) == 0) {
            int rA = m0 + wid * 16 + (lane >> 2);
            int rB = rA + 8;
            size_t cA = (size_t)rA * 24 + nt * 3;
            size_t cB = (size_t)rB * 24 + nt * 3;
            d_cand[cA] = ai0; d_cand[cA + 1] = ai1; d_cand[cA + 2] = ai2;
            d_cand[cB] = bi0; d_cand[cB + 1] = bi1; d_cand[cB + 2] = bi2;
        }
        ins2(a0, ai0, gva0, gia0, gva1, gia1);
        ins2(a1, ai1, gva0, gia0, gva1, gia1);
        ins2(b0, bi0, gvb0, gib0, gvb1, gib1);
        ins2(b1, bi1, gvb0, gib0, gvb1, gib1);
    }

    if ((lane & 3) == 0) {
        int rA = m0 + wid * 16 + (lane >> 2);
        int rB = rA + 8;
        d_smin[rA] = gva0; d_sidx[rA] = gia0;
        d_smin[rB] = gvb0; d_sidx[rB] = gib0;
        if (gva1 - gva0 < 2e-4f) d_amb[atomicAdd(&d_count, 1)] = rA;
        if (gvb1 - gvb0 < 2e-4f) d_amb[atomicAdd(&d_count, 1)] = rB;
    }
}

// ---------------- kernel 3: exact rescore of ambiguous rows ----------------
__global__ void k_rescore(const float* __restrict__ z, const float* __restrict__ cb) {
    int t = blockIdx.x * blockDim.x + threadIdx.x;
    if (t >= d_count) return;
    int row = d_amb[t];
    int b = row >> 12, p = row & 4095;
    const float* base = z + ((size_t)b << 20) + p;

    int cj[24];
#pragma unroll
    for (int q = 0; q < 24; ++q) cj[q] = d_cand[(size_t)row * 24 + q] & 1023;

    float dot[24];
#pragma unroll
    for (int q = 0; q < 24; ++q) dot[q] = 0.f;
    float zn = 0.f;
    for (int k = 0; k < CDIM; ++k) {           // strictly ascending k
        float zv = base[(size_t)k << 12];
        zn = __fadd_rn(zn, __fmul_rn(zv, zv));
#pragma unroll
        for (int q = 0; q < 24; ++q)
            dot[q] = __fmaf_rn(zv, cb[(size_t)cj[q] * CDIM + k], dot[q]);
    }
    float best = FLT_MAX; int bj = 0x7fffffff;
#pragma unroll
    for (int q = 0; q < 24; ++q) {
        float d = __fadd_rn(__fadd_rn(zn, d_cnorm[cj[q]]), -(2.0f * dot[q]));
        if (d < best || (d == best && cj[q] < bj)) { best = d; bj = cj[q]; }
    }
    d_sidx[row] = bj;
}

// ---------------- kernel 4: loss ----------------
__global__ void k_loss(float* __restrict__ out) {
    __shared__ double sh[1024];
    const int t = threadIdx.x;
    double s = 0.0;
#pragma unroll
    for (int j = 0; j < 64; ++j) {
        int i = t + j * 1024;
        s += (double)d_zn[i] + (double)d_smin[i];
    }
    sh[t] = s;
    __syncthreads();
#pragma unroll
    for (int o = 512; o; o >>= 1) {
        if (t < o) sh[t] += sh[t + o];
        __syncthreads();
    }
    if (t == 0) {
        float m = (float)(sh[0] / 16777216.0);
        out[LOSS_OFF] = __fadd_rn(m, __fmul_rn(0.25f, m));
    }
}

// ---------------- kernel 5: gather ----------------
__global__ void k_gather(const float* __restrict__ cb, float* __restrict__ out) {
    __shared__ float sm[32][257];
    __shared__ int js[32];
    const int i0 = blockIdx.x * 32;
    const int b  = i0 >> 12;
    const int p0 = i0 & 4095;
    const int t  = threadIdx.x;

    if (t < 32) js[t] = d_sidx[i0 + t];
    __syncthreads();
#pragma unroll
    for (int s = t; s < 32 * 256; s += 256) {
        int row = s >> 8, col = s & 255;
        sm[row][col] = cb[(size_t)js[row] * CDIM + col];
    }
    __syncthreads();
    float* ob = out + ((size_t)b << 20) + p0;
#pragma unroll
    for (int c0 = 0; c0 < 256; c0 += 8) {
        int c = c0 + (t >> 5);
        int p = t & 31;
        ob[((size_t)c << 12) + p] = sm[p][c];
    }
    if (t < 32) out[IDX_OFF + i0 + t] = (float)js[t];
}

// ---------------- launch ----------------
extern "C" void kernel_launch(void* const* d_in, const int* in_sizes, int n_in,
                              void* d_out, int out_size) {
    const float* z  = (const float*)d_in[0];
    const float* cb = (const float*)d_in[1];
    float* out = (float*)d_out;

    cudaFuncSetAttribute(k_main_mma, cudaFuncAttributeMaxDynamicSharedMemorySize, SM_TOTAL);

    k_cnorm<<<4, 256>>>(cb);
    k_cbconv<<<NE, 256>>>(cb);
    k_convert<<<dim3(8, 128, 16), dim3(32, 8)>>>(z);
    k_znorm<<<NVEC / 256, 256>>>(z);
    k_main_mma<<<NVEC / 128, 256, SM_TOTAL>>>();
    k_rescore<<<512, 128>>>(z, cb);
    k_loss<<<1, 1024>>>(out);
    k_gather<<<NVEC / 32, 256>>>(cb, out);
}